// round 2
// baseline (speedup 1.0000x reference)
#include <cuda_runtime.h>
#include <cuda_bf16.h>

// Scratch (no cudaMalloc allowed): compacted half-scaled predictions + counters + sum.
#define MAX_B 16384
__device__ float g_pos[MAX_B];
__device__ float g_neg[MAX_B];
__device__ int   g_pcnt;
__device__ int   g_ncnt;
__device__ float g_sum;

__device__ __forceinline__ float tanh_apx(float x) {
    float r;
    asm("tanh.approx.f32 %0, %1;" : "=f"(r) : "f"(x));
    return r;
}

__global__ void zero_kernel() {
    g_pcnt = 0;
    g_ncnt = 0;
    g_sum  = 0.0f;
}

// Compact y_pred into pos/neg arrays (storing 0.5*y_pred), warp-aggregated atomics.
__global__ void partition_kernel(const float* __restrict__ y_pred,
                                 const long long* __restrict__ y_true, int B) {
    int i = blockIdx.x * blockDim.x + threadIdx.x;
    bool ispos = false, isneg = false;
    float v = 0.0f;
    if (i < B) {
        v = 0.5f * y_pred[i];
        ispos = (y_true[i] == 1);
        isneg = !ispos;
    }
    unsigned mp = __ballot_sync(0xFFFFFFFFu, ispos);
    unsigned mn = __ballot_sync(0xFFFFFFFFu, isneg);
    int lane = threadIdx.x & 31;
    int basep = 0, basen = 0;
    if (lane == 0) {
        basep = atomicAdd(&g_pcnt, __popc(mp));
        basen = atomicAdd(&g_ncnt, __popc(mn));
    }
    basep = __shfl_sync(0xFFFFFFFFu, basep, 0);
    basen = __shfl_sync(0xFFFFFFFFu, basen, 0);
    unsigned lt = (1u << lane) - 1u;
    if (ispos) g_pos[basep + __popc(mp & lt)] = v;
    if (isneg) g_neg[basen + __popc(mn & lt)] = v;
}

// Pairwise sum of tanh(neg/2 - pos/2). Grid: (ceil(B/256), ceil(B/1024)).
#define POS_TILE 256
#define NEG_CHUNK 1024
__global__ __launch_bounds__(POS_TILE) void pair_kernel() {
    __shared__ float sneg[NEG_CHUNK];
    __shared__ float wsum[POS_TILE / 32];

    int p = g_pcnt;
    int n = g_ncnt;

    int pos_base = blockIdx.x * POS_TILE;
    int neg_base = blockIdx.y * NEG_CHUNK;
    if (pos_base >= p || neg_base >= n) return;  // uniform per block

    int jmax = n - neg_base;
    if (jmax > NEG_CHUNK) jmax = NEG_CHUNK;

    for (int j = threadIdx.x; j < jmax; j += POS_TILE)
        sneg[j] = g_neg[neg_base + j];
    __syncthreads();

    int i = pos_base + threadIdx.x;
    bool active = (i < p);
    float ph = active ? g_pos[i] : 0.0f;

    float a0 = 0.f, a1 = 0.f, a2 = 0.f, a3 = 0.f;
    int j = 0;
    for (; j + 8 <= jmax; j += 8) {
        float t0 = tanh_apx(sneg[j + 0] - ph);
        float t1 = tanh_apx(sneg[j + 1] - ph);
        float t2 = tanh_apx(sneg[j + 2] - ph);
        float t3 = tanh_apx(sneg[j + 3] - ph);
        float t4 = tanh_apx(sneg[j + 4] - ph);
        float t5 = tanh_apx(sneg[j + 5] - ph);
        float t6 = tanh_apx(sneg[j + 6] - ph);
        float t7 = tanh_apx(sneg[j + 7] - ph);
        a0 += t0; a1 += t1; a2 += t2; a3 += t3;
        a0 += t4; a1 += t5; a2 += t6; a3 += t7;
    }
    for (; j < jmax; ++j)
        a0 += tanh_apx(sneg[j] - ph);

    float acc = active ? ((a0 + a1) + (a2 + a3)) : 0.0f;

    // warp reduce
    #pragma unroll
    for (int off = 16; off > 0; off >>= 1)
        acc += __shfl_xor_sync(0xFFFFFFFFu, acc, off);

    int warp = threadIdx.x >> 5;
    if ((threadIdx.x & 31) == 0) wsum[warp] = acc;
    __syncthreads();
    if (threadIdx.x == 0) {
        float s = 0.0f;
        #pragma unroll
        for (int w = 0; w < POS_TILE / 32; ++w) s += wsum[w];
        atomicAdd(&g_sum, s);
    }
}

__global__ void finalize_kernel(float* __restrict__ out) {
    float p = (float)g_pcnt;
    float n = (float)g_ncnt;
    out[0] = 0.5f + g_sum / (2.0f * p * n);
}

extern "C" void kernel_launch(void* const* d_in, const int* in_sizes, int n_in,
                              void* d_out, int out_size) {
    const float*     y_pred = (const float*)d_in[0];
    const long long* y_true = (const long long*)d_in[1];
    float* out = (float*)d_out;
    int B = in_sizes[0];

    zero_kernel<<<1, 1>>>();
    partition_kernel<<<(B + 255) / 256, 256>>>(y_pred, y_true, B);
    dim3 grid((B + POS_TILE - 1) / POS_TILE, (B + NEG_CHUNK - 1) / NEG_CHUNK);
    pair_kernel<<<grid, POS_TILE>>>();
    finalize_kernel<<<1, 1>>>(out);
}

// round 5
// speedup vs baseline: 1.3313x; 1.3313x over previous
#include <cuda_runtime.h>
#include <cuda_bf16.h>

// ---- persistent scratch (no allocs allowed) ----
#define MAX_B 16384
__device__ float g_pos[MAX_B];
__device__ float g_neg[MAX_B];
__device__ int   g_pcnt  = 0;
__device__ int   g_ncnt  = 0;
__device__ int   g_bar   = 0;   // phase barrier arrival count
__device__ int   g_ticket = 0;  // tile work-stealing ticket
__device__ int   g_done  = 0;   // finish count
__device__ float g_sum   = 0.0f;

#define NBLK 296
#define NTHR 256
#define NEG_CHUNK 128

__device__ __forceinline__ float tanh_apx(float x) {
    float r;
    asm("tanh.approx.f32 %0, %1;" : "=f"(r) : "f"(x));
    return r;
}

__global__ __launch_bounds__(NTHR) void auc_fused_kernel(
    const float* __restrict__ y_pred,
    const long long* __restrict__ y_true,
    int B, float* __restrict__ out)
{
    const int tid = threadIdx.x;
    const int gsz = gridDim.x * NTHR;

    // ================= Phase 1: partition (warp-aggregated compaction) ======
    // Uniform trip count so ballots are full-warp.
    int iters = (B + gsz - 1) / gsz;
    for (int it = 0; it < iters; ++it) {
        int i = blockIdx.x * NTHR + tid + it * gsz;
        bool ispos = false, isneg = false;
        float v = 0.0f;
        if (i < B) {
            v = 0.5f * y_pred[i];
            ispos = (y_true[i] == 1);
            isneg = !ispos;
        }
        unsigned mp = __ballot_sync(0xFFFFFFFFu, ispos);
        unsigned mn = __ballot_sync(0xFFFFFFFFu, isneg);
        int lane = tid & 31;
        int basep = 0, basen = 0;
        if (lane == 0) {
            basep = atomicAdd(&g_pcnt, __popc(mp));
            basen = atomicAdd(&g_ncnt, __popc(mn));
        }
        basep = __shfl_sync(0xFFFFFFFFu, basep, 0);
        basen = __shfl_sync(0xFFFFFFFFu, basen, 0);
        unsigned lt = (1u << lane) - 1u;
        if (ispos) g_pos[basep + __popc(mp & lt)] = v;
        if (isneg) g_neg[basen + __popc(mn & lt)] = v;
    }

    // ================= grid barrier ========================================
    __threadfence();          // make this thread's writes device-visible
    __syncthreads();
    if (tid == 0) {
        atomicAdd(&g_bar, 1);
        while (*((volatile int*)&g_bar) < (int)gridDim.x) { /* spin */ }
    }
    __syncthreads();
    __threadfence();

    // ================= Phase 2: pairwise tanh sum (work-stealing tiles) ====
    const int p = g_pcnt;
    const int n = g_ncnt;
    const int ntp = (p + NTHR - 1) / NTHR;
    const int ntn = (n + NEG_CHUNK - 1) / NEG_CHUNK;
    const int ntiles = ntp * ntn;

    __shared__ float sneg[NEG_CHUNK];
    __shared__ int   s_tile;
    __shared__ float wsum[NTHR / 32];

    float A0 = 0.f, A1 = 0.f, A2 = 0.f, A3 = 0.f;

    for (;;) {
        if (tid == 0) s_tile = atomicAdd(&g_ticket, 1);
        __syncthreads();                // also protects sneg reuse
        int t = s_tile;
        if (t >= ntiles) break;
        int tp = t / ntn;
        int tn = t - tp * ntn;

        int nb = tn * NEG_CHUNK;
        int jmax = n - nb; if (jmax > NEG_CHUNK) jmax = NEG_CHUNK;
        if (tid < jmax) sneg[tid] = g_neg[nb + tid];
        __syncthreads();

        int i = tp * NTHR + tid;
        bool active = (i < p);
        float ph = active ? g_pos[i] : 0.0f;

        float a0 = 0.f, a1 = 0.f, a2 = 0.f, a3 = 0.f;
        int j = 0;
        for (; j + 8 <= jmax; j += 8) {
            float t0 = tanh_apx(sneg[j + 0] - ph);
            float t1 = tanh_apx(sneg[j + 1] - ph);
            float t2 = tanh_apx(sneg[j + 2] - ph);
            float t3 = tanh_apx(sneg[j + 3] - ph);
            float t4 = tanh_apx(sneg[j + 4] - ph);
            float t5 = tanh_apx(sneg[j + 5] - ph);
            float t6 = tanh_apx(sneg[j + 6] - ph);
            float t7 = tanh_apx(sneg[j + 7] - ph);
            a0 += t0; a1 += t1; a2 += t2; a3 += t3;
            a0 += t4; a1 += t5; a2 += t6; a3 += t7;
        }
        for (; j < jmax; ++j)
            a0 += tanh_apx(sneg[j] - ph);

        if (active) { A0 += a0; A1 += a1; A2 += a2; A3 += a3; }
    }

    // ================= block reduce + finalize =============================
    float acc = (A0 + A1) + (A2 + A3);
    #pragma unroll
    for (int off = 16; off > 0; off >>= 1)
        acc += __shfl_xor_sync(0xFFFFFFFFu, acc, off);
    if ((tid & 31) == 0) wsum[tid >> 5] = acc;
    __syncthreads();

    if (tid == 0) {
        float s = 0.0f;
        #pragma unroll
        for (int w = 0; w < NTHR / 32; ++w) s += wsum[w];
        atomicAdd(&g_sum, s);
        __threadfence();
        int r = atomicAdd(&g_done, 1);
        if (r == (int)gridDim.x - 1) {
            __threadfence();
            float total = *((volatile float*)&g_sum);
            out[0] = 0.5f + total / (2.0f * (float)p * (float)n);
            // reset state for next (deterministic) graph replay
            g_pcnt = 0; g_ncnt = 0; g_sum = 0.0f;
            g_bar = 0; g_ticket = 0; g_done = 0;
            __threadfence();
        }
    }
}

extern "C" void kernel_launch(void* const* d_in, const int* in_sizes, int n_in,
                              void* d_out, int out_size) {
    const float*     y_pred = (const float*)d_in[0];
    const long long* y_true = (const long long*)d_in[1];
    float* out = (float*)d_out;
    int B = in_sizes[0];

    auc_fused_kernel<<<NBLK, NTHR>>>(y_pred, y_true, B, out);
}

// round 11
// speedup vs baseline: 1.3436x; 1.0092x over previous
#include <cuda_runtime.h>
#include <cuda_bf16.h>
#include <cstdint>

// ---- persistent scratch (no allocs allowed) ----
#define MAX_B 16384
__device__ float g_pos[MAX_B];
__device__ float g_neg[MAX_B];
__device__ int   g_pcnt = 0;
__device__ int   g_ncnt = 0;
__device__ int   g_bar  = 0;   // phase barrier arrival count
__device__ int   g_done = 0;   // finish count
__device__ float g_sum  = 0.0f;

#define NBLK 296
#define NTHR 256
#define NEG_CHUNK 128

__device__ __forceinline__ float tanh_apx(float x) {
    float r;
    asm("tanh.approx.f32 %0, %1;" : "=f"(r) : "f"(x));
    return r;
}

__device__ __forceinline__ void cpa16(void* smem_dst, const void* gmem_src) {
    unsigned int d = (unsigned int)__cvta_generic_to_shared(smem_dst);
    asm volatile("cp.async.cg.shared.global [%0], [%1], 16;" :: "r"(d), "l"(gmem_src));
}

__global__ __launch_bounds__(NTHR) void auc_fused_kernel(
    const float* __restrict__ y_pred,
    const long long* __restrict__ y_true,
    int B, float* __restrict__ out)
{
    const int tid = threadIdx.x;
    const int gsz = gridDim.x * NTHR;

    // ================= Phase 1: partition (warp-aggregated compaction) ======
    int iters = (B + gsz - 1) / gsz;
    for (int it = 0; it < iters; ++it) {
        int i = blockIdx.x * NTHR + tid + it * gsz;
        bool ispos = false, isneg = false;
        float v = 0.0f;
        if (i < B) {
            v = 0.5f * y_pred[i];
            ispos = (y_true[i] == 1);
            isneg = !ispos;
        }
        unsigned mp = __ballot_sync(0xFFFFFFFFu, ispos);
        unsigned mn = __ballot_sync(0xFFFFFFFFu, isneg);
        int lane = tid & 31;
        int basep = 0, basen = 0;
        if (lane == 0) {
            basep = atomicAdd(&g_pcnt, __popc(mp));
            basen = atomicAdd(&g_ncnt, __popc(mn));
        }
        basep = __shfl_sync(0xFFFFFFFFu, basep, 0);
        basen = __shfl_sync(0xFFFFFFFFu, basen, 0);
        unsigned lt = (1u << lane) - 1u;
        if (ispos) g_pos[basep + __popc(mp & lt)] = v;
        if (isneg) g_neg[basen + __popc(mn & lt)] = v;
    }

    // ================= grid barrier ========================================
    __threadfence();
    __syncthreads();
    if (tid == 0) {
        atomicAdd(&g_bar, 1);
        while (*((volatile int*)&g_bar) < (int)gridDim.x) { /* spin */ }
    }
    __syncthreads();
    __threadfence();

    // ================= Phase 2: static interleaved tiles, cp.async pipeline =
    const int p = g_pcnt;
    const int n = g_ncnt;
    const int ntp = (p + NTHR - 1) / NTHR;
    const int ntn = (n + NEG_CHUNK - 1) / NEG_CHUNK;
    const int ntiles = ntp * ntn;

    __shared__ float sneg[2][NEG_CHUNK];
    __shared__ float wsum[NTHR / 32];

    float A0 = 0.f, A1 = 0.f, A2 = 0.f, A3 = 0.f;

    int t = blockIdx.x;

    // preload first tile's negs (warp 0: 32 x 16B = 512B)
    if (tid < 32) {
        if (t < ntiles) {
            int tn = t % ntn;
            cpa16(&sneg[0][tid * 4], &g_neg[tn * NEG_CHUNK + tid * 4]);
        }
        asm volatile("cp.async.commit_group;");
        asm volatile("cp.async.wait_group 0;");
    }
    __syncthreads();

    int cur = 0;
    for (; t < ntiles; t += NBLK) {
        // prefetch next tile's negs into the other buffer (overlaps compute)
        int tnext = t + NBLK;
        if (tid < 32) {
            if (tnext < ntiles) {
                int tn2 = tnext % ntn;
                cpa16(&sneg[cur ^ 1][tid * 4], &g_neg[tn2 * NEG_CHUNK + tid * 4]);
            }
            asm volatile("cp.async.commit_group;");
        }

        int tp = t / ntn;
        int tn = t - tp * ntn;
        int nb = tn * NEG_CHUNK;
        int jmax = n - nb; if (jmax > NEG_CHUNK) jmax = NEG_CHUNK;

        int i = tp * NTHR + tid;
        bool active = (i < p);
        float ph = active ? g_pos[i] : 0.0f;
        const float* sn = sneg[cur];

        float a0 = 0.f, a1 = 0.f, a2 = 0.f, a3 = 0.f;
        if (jmax == NEG_CHUNK) {
            for (int j = 0; j < NEG_CHUNK; j += 8) {
                float t0 = tanh_apx(sn[j + 0] - ph);
                float t1 = tanh_apx(sn[j + 1] - ph);
                float t2 = tanh_apx(sn[j + 2] - ph);
                float t3 = tanh_apx(sn[j + 3] - ph);
                float t4 = tanh_apx(sn[j + 4] - ph);
                float t5 = tanh_apx(sn[j + 5] - ph);
                float t6 = tanh_apx(sn[j + 6] - ph);
                float t7 = tanh_apx(sn[j + 7] - ph);
                a0 += t0; a1 += t1; a2 += t2; a3 += t3;
                a0 += t4; a1 += t5; a2 += t6; a3 += t7;
            }
        } else {
            for (int j = 0; j < jmax; ++j)
                a0 += tanh_apx(sn[j] - ph);
        }
        if (active) { A0 += a0; A1 += a1; A2 += a2; A3 += a3; }

        if (tid < 32) asm volatile("cp.async.wait_group 0;");
        __syncthreads();
        cur ^= 1;
    }

    // ================= block reduce + finalize =============================
    float acc = (A0 + A1) + (A2 + A3);
    #pragma unroll
    for (int off = 16; off > 0; off >>= 1)
        acc += __shfl_xor_sync(0xFFFFFFFFu, acc, off);
    if ((tid & 31) == 0) wsum[tid >> 5] = acc;
    __syncthreads();

    if (tid == 0) {
        float s = 0.0f;
        #pragma unroll
        for (int w = 0; w < NTHR / 32; ++w) s += wsum[w];
        atomicAdd(&g_sum, s);
        __threadfence();
        int r = atomicAdd(&g_done, 1);
        if (r == (int)gridDim.x - 1) {
            __threadfence();
            float total = *((volatile float*)&g_sum);
            out[0] = 0.5f + total / (2.0f * (float)p * (float)n);
            // reset state for next (deterministic) graph replay
            g_pcnt = 0; g_ncnt = 0; g_sum = 0.0f;
            g_bar = 0; g_done = 0;
            __threadfence();
        }
    }
}

extern "C" void kernel_launch(void* const* d_in, const int* in_sizes, int n_in,
                              void* d_out, int out_size) {
    const float*     y_pred = (const float*)d_in[0];
    const long long* y_true = (const long long*)d_in[1];
    float* out = (float*)d_out;
    int B = in_sizes[0];

    auc_fused_kernel<<<NBLK, NTHR>>>(y_pred, y_true, B, out);
}